// round 8
// baseline (speedup 1.0000x reference)
#include <cuda_runtime.h>
#include <cuda_bf16.h>
#include <math.h>
#include <stdint.h>

#define NTOK 8192
#define DIM  1024
#define INV_SCALE 0.08838834764831843f   // 1/sqrt(128)

// ---------------------------------------------------------------------------
// Scratch (device globals; no allocation allowed)
// ---------------------------------------------------------------------------
__device__ __nv_bfloat16 g_xb[(size_t)NTOK * DIM];
__device__ __nv_bfloat16 g_wqb[(size_t)DIM * DIM];
__device__ __nv_bfloat16 g_wkb[(size_t)DIM * DIM];
__device__ __nv_bfloat16 g_wvb[(size_t)DIM * DIM];
__device__ __nv_bfloat16 g_wob[(size_t)DIM * DIM];
__device__ __nv_bfloat16 g_qb[(size_t)NTOK * DIM];
__device__ __nv_bfloat16 g_kb[(size_t)NTOK * DIM];
__device__ __nv_bfloat16 g_vb[(size_t)NTOK * DIM];
__device__ __nv_bfloat16 g_vT[(size_t)DIM * NTOK];   // [DIM, NTOK]
__device__ __nv_bfloat16 g_ob[(size_t)NTOK * DIM];
__device__ __nv_bfloat16 g_att[(size_t)NTOK * NTOK]; // exp(z*inv_scale), unnormalized
__device__ float g_rs[NTOK];                         // row sums of exp

// ---------------------------------------------------------------------------
// Helpers
// ---------------------------------------------------------------------------
__device__ __forceinline__ uint32_t smem_u32(const void* p) {
    uint32_t a;
    asm("{ .reg .u64 t; cvta.to.shared.u64 t, %1; cvt.u32.u64 %0, t; }" : "=r"(a) : "l"(p));
    return a;
}
__device__ __forceinline__ uint32_t swz(uint32_t x) { return x ^ ((x >> 3) & 0x70); }

__device__ __forceinline__ void cp16(uint32_t saddr, const void* g) {
    asm volatile("cp.async.cg.shared.global [%0], [%1], 16;\n" :: "r"(saddr), "l"(g));
}
__device__ __forceinline__ void cp_commit() { asm volatile("cp.async.commit_group;\n" ::); }
template <int N> __device__ __forceinline__ void cp_wait() {
    asm volatile("cp.async.wait_group %0;\n" :: "n"(N));
}

__device__ __forceinline__ void ldsm_x4(uint32_t addr, uint32_t* r) {
    asm volatile("ldmatrix.sync.aligned.m8n8.x4.shared.b16 {%0,%1,%2,%3}, [%4];"
        : "=r"(r[0]), "=r"(r[1]), "=r"(r[2]), "=r"(r[3]) : "r"(addr));
}

__device__ __forceinline__ void mma_bf16(float* c, const uint32_t* a, const uint32_t* b) {
    asm volatile("mma.sync.aligned.m16n8k16.row.col.f32.bf16.bf16.f32 "
        "{%0,%1,%2,%3}, {%4,%5,%6,%7}, {%8,%9}, {%0,%1,%2,%3};"
        : "+f"(c[0]), "+f"(c[1]), "+f"(c[2]), "+f"(c[3])
        : "r"(a[0]), "r"(a[1]), "r"(a[2]), "r"(a[3]), "r"(b[0]), "r"(b[1]));
}

__device__ __forceinline__ uint32_t pack_bf16(float lo, float hi) {
    uint32_t r;
    asm("cvt.rn.bf16x2.f32 %0, %1, %2;" : "=r"(r) : "f"(hi), "f"(lo));
    return r;
}

// ---------------------------------------------------------------------------
// bf16 mma.sync GEMM body:  C[M,Nn] = A[M,K] @ B[Nn,K]^T  (K-major bf16)
// CTA 128x256, BK=64, 3-stage cp.async, one __syncthreads per k-tile,
// 256 threads = 8 warps (2M x 4N), warp tile 64x64, frag double-buffering.
// ---------------------------------------------------------------------------
#define BM 128
#define BN 256
#define BK 64
#define A_ST_BYTES (BM * 128)                    // 16384
#define B_ST_BYTES (BN * 128)                    // 32768
#define SMEM_B_OFF (3 * A_ST_BYTES)              // 49152
#define SMEM_TOTAL (SMEM_B_OFF + 3 * B_ST_BYTES) // 147456

enum { EPI_BF16 = 0, EPI_EXP = 1, EPI_SCALE = 2, EPI_OUT = 3 };

template <int EPI>
__device__ __forceinline__ void gemm_body(
    const __nv_bfloat16* __restrict__ A,
    const __nv_bfloat16* __restrict__ B,
    const float* __restrict__ bias,
    const float* __restrict__ res,
    const float* __restrict__ rs,
    void* __restrict__ Cv,
    int Nn, int K, int bm, int bn, char* smem)
{
    const uint32_t sb = smem_u32(smem);
    const int tid = threadIdx.x, lane = tid & 31, wid = tid >> 5;
    const int wn = wid & 3, wm = wid >> 2;       // 2 (M) x 4 (N)

    float acc[4][8][4];
    #pragma unroll
    for (int i = 0; i < 4; i++)
        #pragma unroll
        for (int j = 0; j < 8; j++)
            #pragma unroll
            for (int q = 0; q < 4; q++) acc[i][j][q] = 0.0f;

    const int KT = K / BK;

    auto load_stage = [&](int s, int kt) {
        const int k0 = kt * BK;
        const uint32_t ab = sb + s * A_ST_BYTES;
        const __nv_bfloat16* Ag = A + (size_t)bm * K + k0;
        #pragma unroll
        for (int i = 0; i < 4; i++) {
            int c = tid + (i << 8);
            int r = c >> 3, kc = c & 7;
            cp16(ab + swz((r << 7) + (kc << 4)), Ag + (size_t)r * K + (kc << 3));
        }
        const uint32_t bb = sb + SMEM_B_OFF + s * B_ST_BYTES;
        const __nv_bfloat16* Bg = B + (size_t)bn * K + k0;
        #pragma unroll
        for (int i = 0; i < 8; i++) {
            int c = tid + (i << 8);
            int r = c >> 3, kc = c & 7;
            cp16(bb + swz((r << 7) + (kc << 4)), Bg + (size_t)r * K + (kc << 3));
        }
        cp_commit();
    };

    load_stage(0, 0);
    load_stage(1, 1);

    // per-lane ldmatrix offsets
    const int g = lane >> 3, r8 = lane & 7;
    const int a_row = wm * 64 + (g & 1) * 8 + r8;     // + mt*16
    const int a_kb  = (g >> 1) * 16;                  // + ks*32
    const int b_row = wn * 64 + (g >> 1) * 8 + r8;    // + np*16
    const int b_kb  = (g & 1) * 16;                   // + ks*32

    uint32_t a[2][4][4], b[2][4][4];

    int s = 0;
    for (int kt = 0; kt < KT; kt++) {
        if (kt + 1 < KT) cp_wait<1>(); else cp_wait<0>();
        __syncthreads();   // stage s ready; stage (kt+2)%3 safe to overwrite

        if (kt + 2 < KT) load_stage((kt + 2) % 3, kt + 2);

        const uint32_t abase = sb + s * A_ST_BYTES;
        const uint32_t bbase = sb + SMEM_B_OFF + s * B_ST_BYTES;

        // prime frags for ks=0
        #pragma unroll
        for (int mt = 0; mt < 4; mt++)
            ldsm_x4(abase + swz(((a_row + mt * 16) << 7) + a_kb), a[0][mt]);
        #pragma unroll
        for (int np = 0; np < 4; np++)
            ldsm_x4(bbase + swz(((b_row + np * 16) << 7) + b_kb), b[0][np]);

        #pragma unroll
        for (int ks = 0; ks < 4; ks++) {
            const int cur = ks & 1;
            if (ks < 3) {
                const int nxt = cur ^ 1;
                #pragma unroll
                for (int mt = 0; mt < 4; mt++)
                    ldsm_x4(abase + swz(((a_row + mt * 16) << 7) + (ks + 1) * 32 + a_kb), a[nxt][mt]);
                #pragma unroll
                for (int np = 0; np < 4; np++)
                    ldsm_x4(bbase + swz(((b_row + np * 16) << 7) + (ks + 1) * 32 + b_kb), b[nxt][np]);
            }
            #pragma unroll
            for (int mt = 0; mt < 4; mt++)
                #pragma unroll
                for (int np = 0; np < 4; np++) {
                    mma_bf16(acc[mt][np * 2],     a[cur][mt], &b[cur][np][0]);
                    mma_bf16(acc[mt][np * 2 + 1], a[cur][mt], &b[cur][np][2]);
                }
        }
        s++; if (s == 3) s = 0;
    }

    // ---- epilogue ----
    const int lr = lane >> 2, lc = (lane & 3) * 2;

    #pragma unroll
    for (int mt = 0; mt < 4; mt++) {
        #pragma unroll
        for (int h = 0; h < 2; h++) {
            const int row = bm + wm * 64 + mt * 16 + h * 8 + lr;
            float rcp = 0.0f;
            if (EPI == EPI_SCALE) rcp = 1.0f / rs[row];
            #pragma unroll
            for (int nt = 0; nt < 8; nt++) {
                const int col = bn + wn * 64 + nt * 8 + lc;
                float v0 = acc[mt][nt][h * 2];
                float v1 = acc[mt][nt][h * 2 + 1];
                if (EPI == EPI_EXP) {
                    v0 = __expf(v0 * INV_SCALE);
                    v1 = __expf(v1 * INV_SCALE);
                    uint32_t* dst = (uint32_t*)((__nv_bfloat16*)Cv + (size_t)row * Nn + col);
                    *dst = pack_bf16(v0, v1);
                } else if (EPI == EPI_SCALE) {
                    uint32_t* dst = (uint32_t*)((__nv_bfloat16*)Cv + (size_t)row * Nn + col);
                    *dst = pack_bf16(v0 * rcp, v1 * rcp);
                } else if (EPI == EPI_BF16) {
                    v0 += bias[col]; v1 += bias[col + 1];
                    uint32_t* dst = (uint32_t*)((__nv_bfloat16*)Cv + (size_t)row * Nn + col);
                    *dst = pack_bf16(v0, v1);
                } else { // EPI_OUT
                    const float2 rv = *(const float2*)(res + (size_t)row * Nn + col);
                    v0 += bias[col]     + rv.x;
                    v1 += bias[col + 1] + rv.y;
                    float2* dst = (float2*)((float*)Cv + (size_t)row * Nn + col);
                    *dst = make_float2(v0, v1);
                }
            }
        }
    }
}

// single-GEMM wrapper
template <int EPI>
__global__ __launch_bounds__(256)
void gemm_one(const __nv_bfloat16* __restrict__ A,
              const __nv_bfloat16* __restrict__ B,
              const float* __restrict__ bias,
              const float* __restrict__ res,
              const float* __restrict__ rs,
              void* __restrict__ Cv,
              int Nn, int K)
{
    extern __shared__ char smem[];
    gemm_body<EPI>(A, B, bias, res, rs, Cv, Nn, K,
                   blockIdx.y * BM, blockIdx.x * BN, smem);
}

// fused q/k/v projection: blockIdx.z selects the weight/bias/output
__global__ __launch_bounds__(256)
void gemm_qkv(const __nv_bfloat16* __restrict__ xb,
              const __nv_bfloat16* __restrict__ wq,
              const __nv_bfloat16* __restrict__ wk,
              const __nv_bfloat16* __restrict__ wv,
              const float* __restrict__ bq,
              const float* __restrict__ bk,
              const float* __restrict__ bv,
              __nv_bfloat16* __restrict__ qb,
              __nv_bfloat16* __restrict__ kb,
              __nv_bfloat16* __restrict__ vb)
{
    extern __shared__ char smem[];
    const __nv_bfloat16* B;
    const float* bias;
    __nv_bfloat16* C;
    if (blockIdx.z == 0)      { B = wq; bias = bq; C = qb; }
    else if (blockIdx.z == 1) { B = wk; bias = bk; C = kb; }
    else                      { B = wv; bias = bv; C = vb; }
    gemm_body<EPI_BF16>(xb, B, bias, nullptr, nullptr, C, DIM, DIM,
                        blockIdx.y * BM, blockIdx.x * BN, smem);
}

// ---------------------------------------------------------------------------
// All f32 -> bf16 converts in ONE launch. blockIdx.y: 0 = x, 1..4 = weights.
// ---------------------------------------------------------------------------
__global__ __launch_bounds__(256)
void conv_all(const float* __restrict__ x,
              const float* __restrict__ w0, const float* __restrict__ w1,
              const float* __restrict__ w2, const float* __restrict__ w3,
              __nv_bfloat16* __restrict__ xo,
              __nv_bfloat16* __restrict__ o0, __nv_bfloat16* __restrict__ o1,
              __nv_bfloat16* __restrict__ o2, __nv_bfloat16* __restrict__ o3)
{
    const int which = blockIdx.y;
    const float* in; __nv_bfloat16* out; int n4;
    if (which == 0)      { in = x;  out = xo; n4 = NTOK * DIM / 4; }
    else if (which == 1) { in = w0; out = o0; n4 = DIM * DIM / 4; }
    else if (which == 2) { in = w1; out = o1; n4 = DIM * DIM / 4; }
    else if (which == 3) { in = w2; out = o2; n4 = DIM * DIM / 4; }
    else                 { in = w3; out = o3; n4 = DIM * DIM / 4; }
    int i = blockIdx.x * blockDim.x + threadIdx.x;
    if (i >= n4) return;
    float4 v = reinterpret_cast<const float4*>(in)[i];
    uint2 o;
    o.x = pack_bf16(v.x, v.y);
    o.y = pack_bf16(v.z, v.w);
    reinterpret_cast<uint2*>(out)[i] = o;
}

// ---------------------------------------------------------------------------
// bf16 transpose: in[NTOK][DIM] -> out[DIM][NTOK]
// ---------------------------------------------------------------------------
__global__ __launch_bounds__(256)
void transpose_bf16(const __nv_bfloat16* __restrict__ in, __nv_bfloat16* __restrict__ out)
{
    __shared__ __nv_bfloat16 t[32][33];
    const int bx = blockIdx.x * 32;   // dim
    const int by = blockIdx.y * 32;   // token
    const int x = threadIdx.x, y = threadIdx.y;
    #pragma unroll
    for (int i = 0; i < 32; i += 8)
        t[y + i][x] = in[(size_t)(by + y + i) * DIM + bx + x];
    __syncthreads();
    #pragma unroll
    for (int i = 0; i < 32; i += 8)
        out[(size_t)(bx + y + i) * NTOK + by + x] = t[x][y + i];
}

// ---------------------------------------------------------------------------
// Row sums of att (bf16, unnormalized exp) -> fp32. Deterministic tree.
// ---------------------------------------------------------------------------
__global__ __launch_bounds__(256)
void rowsum_kernel(const __nv_bfloat16* __restrict__ att, float* __restrict__ rs)
{
    const int row = blockIdx.x;
    const uint4* p = reinterpret_cast<const uint4*>(att + (size_t)row * NTOK);
    const int tid = threadIdx.x, lane = tid & 31, warp = tid >> 5;
    __shared__ float red[8];

    float s = 0.0f;
    #pragma unroll
    for (int i = 0; i < 4; i++) {
        uint4 u = p[tid + i * 256];
        float2 f0 = __bfloat1622float2(*reinterpret_cast<__nv_bfloat162*>(&u.x));
        float2 f1 = __bfloat1622float2(*reinterpret_cast<__nv_bfloat162*>(&u.y));
        float2 f2 = __bfloat1622float2(*reinterpret_cast<__nv_bfloat162*>(&u.z));
        float2 f3 = __bfloat1622float2(*reinterpret_cast<__nv_bfloat162*>(&u.w));
        s += ((f0.x + f0.y) + (f1.x + f1.y)) + ((f2.x + f2.y) + (f3.x + f3.y));
    }
    #pragma unroll
    for (int o = 16; o > 0; o >>= 1) s += __shfl_xor_sync(0xFFFFFFFF, s, o);
    if (lane == 0) red[warp] = s;
    __syncthreads();
    if (warp == 0) {
        s = red[lane & 7];
        #pragma unroll
        for (int o = 4; o > 0; o >>= 1) s += __shfl_xor_sync(0xFFFFFFFF, s, o);
        if (lane == 0) rs[row] = s;
    }
}

// ---------------------------------------------------------------------------
// Launch
// ---------------------------------------------------------------------------
extern "C" void kernel_launch(void* const* d_in, const int* in_sizes, int n_in,
                              void* d_out, int out_size)
{
    const float* x  = (const float*)d_in[0];
    const float* Wq = (const float*)d_in[1];
    const float* bq = (const float*)d_in[2];
    const float* Wk = (const float*)d_in[3];
    const float* bk = (const float*)d_in[4];
    const float* Wv = (const float*)d_in[5];
    const float* bv = (const float*)d_in[6];
    const float* Wo = (const float*)d_in[7];
    const float* bo = (const float*)d_in[8];
    float* out = (float*)d_out;

    __nv_bfloat16 *xb, *wqb, *wkb, *wvb, *wob, *qb, *kb, *vb, *vT, *ob, *att;
    float* rs;
    cudaGetSymbolAddress((void**)&xb,  g_xb);
    cudaGetSymbolAddress((void**)&wqb, g_wqb);
    cudaGetSymbolAddress((void**)&wkb, g_wkb);
    cudaGetSymbolAddress((void**)&wvb, g_wvb);
    cudaGetSymbolAddress((void**)&wob, g_wob);
    cudaGetSymbolAddress((void**)&qb,  g_qb);
    cudaGetSymbolAddress((void**)&kb,  g_kb);
    cudaGetSymbolAddress((void**)&vb,  g_vb);
    cudaGetSymbolAddress((void**)&vT,  g_vT);
    cudaGetSymbolAddress((void**)&ob,  g_ob);
    cudaGetSymbolAddress((void**)&att, g_att);
    cudaGetSymbolAddress((void**)&rs,  g_rs);

    cudaFuncSetAttribute(gemm_one<EPI_EXP>,   cudaFuncAttributeMaxDynamicSharedMemorySize, SMEM_TOTAL);
    cudaFuncSetAttribute(gemm_one<EPI_SCALE>, cudaFuncAttributeMaxDynamicSharedMemorySize, SMEM_TOTAL);
    cudaFuncSetAttribute(gemm_one<EPI_OUT>,   cudaFuncAttributeMaxDynamicSharedMemorySize, SMEM_TOTAL);
    cudaFuncSetAttribute(gemm_qkv,            cudaFuncAttributeMaxDynamicSharedMemorySize, SMEM_TOTAL);

    dim3 blk(256);
    dim3 g_proj(DIM / BN, NTOK / BM);     // (4, 64)
    dim3 g_qkv(DIM / BN, NTOK / BM, 3);   // (4, 64, 3)
    dim3 g_scores(NTOK / BN, NTOK / BM);  // (32, 64)

    // 1: all converts
    {
        int gx = (NTOK * DIM / 4 + 255) / 256;
        conv_all<<<dim3(gx, 5), 256>>>(x, Wq, Wk, Wv, Wo, xb, wqb, wkb, wvb, wob);
    }

    // 2: fused q/k/v projections
    gemm_qkv<<<g_qkv, blk, SMEM_TOTAL>>>(xb, wqb, wkb, wvb, bq, bk, bv, qb, kb, vb);

    // 3: vT = vb^T
    {
        dim3 tb(32, 8);
        dim3 tg(DIM / 32, NTOK / 32);
        transpose_bf16<<<tg, tb>>>(vb, vT);
    }

    // 4: att = exp((q @ k^T) * inv_scale)
    gemm_one<EPI_EXP><<<g_scores, blk, SMEM_TOTAL>>>(qb, kb, nullptr, nullptr, nullptr, att, NTOK, DIM);

    // 5: rs[row] = sum of att row
    rowsum_kernel<<<NTOK, 256>>>(att, rs);

    // 6: o = (att @ vT^T) * (1/rs[row])
    gemm_one<EPI_SCALE><<<g_proj, blk, SMEM_TOTAL>>>(att, vT, nullptr, nullptr, rs, ob, DIM, NTOK);

    // 7: out = o @ Wo^T + bo + x
    gemm_one<EPI_OUT><<<g_proj, blk, SMEM_TOTAL>>>(ob, wob, bo, x, nullptr, out, DIM, DIM);
}